// round 10
// baseline (speedup 1.0000x reference)
#include <cuda_runtime.h>
#include <math.h>

#define B_   32
#define TT_  512
#define TM_  2048
#define D_   512
#define M_   80
#define NEGF (-1e9f)

#define HEXP_ELEMS (B_*TM_*D_)       /* 33554432 */
#define LOSS_OFF   HEXP_ELEMS
#define DUR_OFF    (HEXP_ELEMS + 1)

typedef unsigned long long ull;

// ------------------- device scratch (no allocation allowed) -------------------
__device__ float g_hw[B_*TT_*M_];         // [b*Tt+i][80] = h @ W
__device__ float g_hb[B_*TT_];            // h @ b_proj
__device__ float g_S[(size_t)B_*TM_*TT_]; // [b][j][i] masked scores (128 MB)
__device__ int   g_idx[B_*TM_];           // frame -> token index
__device__ float g_lsq[B_];
__device__ float g_lcnt[B_];

// ------------------- f32x2 helpers -------------------
__device__ __forceinline__ ull pk2(float x, float y) {
    ull r;
    asm("mov.b64 %0, {%1,%2};" : "=l"(r) : "f"(x), "f"(y));
    return r;
}
__device__ __forceinline__ float2 upk2(ull v) {
    float2 r;
    asm("mov.b64 {%0,%1}, %2;" : "=f"(r.x), "=f"(r.y) : "l"(v));
    return r;
}
#define FMA2(d, a, b, c) asm("fma.rn.f32x2 %0, %1, %2, %3;" : "=l"(d) : "l"(a), "l"(b), "l"(c))

// =================== K1: hw[b,i,m] = sum_d h[b,i,d] * w[d,m]  (frozen) ===================
__global__ void __launch_bounds__(256) k1_hw(const float* __restrict__ h,
                                             const float* __restrict__ w) {
    __shared__ float hS[64*68];   // [r][d] stride 68
    __shared__ float wS[64*84];   // [d][m] stride 84
    int tid  = threadIdx.x;
    int row0 = blockIdx.x * 64;
    int tx = tid & 15;
    int ty = tid >> 4;
    float acc[4][5];
#pragma unroll
    for (int r = 0; r < 4; r++)
#pragma unroll
        for (int m = 0; m < 5; m++) acc[r][m] = 0.f;

    for (int dc = 0; dc < D_; dc += 64) {
#pragma unroll
        for (int k = 0; k < 4; k++) {
            int l = tid + k*256;
            int r = l >> 4, d4 = l & 15;
            float4 v = *(const float4*)&h[(size_t)(row0 + r)*D_ + dc + d4*4];
            *(float4*)&hS[r*68 + d4*4] = v;
        }
#pragma unroll
        for (int k = 0; k < 5; k++) {
            int l = tid + k*256;
            int d = l / 20, m4 = l % 20;
            float4 v = *(const float4*)&w[(size_t)(dc + d)*M_ + m4*4];
            *(float4*)&wS[d*84 + m4*4] = v;
        }
        __syncthreads();
#pragma unroll 8
        for (int d = 0; d < 64; d++) {
            float a0 = hS[(ty*4+0)*68 + d];
            float a1 = hS[(ty*4+1)*68 + d];
            float a2 = hS[(ty*4+2)*68 + d];
            float a3 = hS[(ty*4+3)*68 + d];
#pragma unroll
            for (int m = 0; m < 5; m++) {
                float bv = wS[d*84 + tx*5 + m];
                acc[0][m] += a0*bv; acc[1][m] += a1*bv;
                acc[2][m] += a2*bv; acc[3][m] += a3*bv;
            }
        }
        __syncthreads();
    }
#pragma unroll
    for (int r = 0; r < 4; r++)
#pragma unroll
        for (int m = 0; m < 5; m++)
            g_hw[(size_t)(row0 + ty*4 + r)*M_ + tx*5 + m] = acc[r][m];
}

// =================== K1b: hb[row] = h[row,:] . b_proj  (frozen) ===================
__global__ void k1_hb(const float* __restrict__ h, const float* __restrict__ bp) {
    int gw   = (blockIdx.x*blockDim.x + threadIdx.x) >> 5;
    int lane = threadIdx.x & 31;
    if (gw >= B_*TT_) return;
    const float4* hr = (const float4*)&h[(size_t)gw * D_];
    const float4* b4 = (const float4*)bp;
    float s = 0.f;
    for (int k = lane; k < D_/4; k += 32) {
        float4 a = hr[k], c = b4[k];
        s += a.x*c.x + a.y*c.y + a.z*c.z + a.w*c.w;
    }
#pragma unroll
    for (int o = 16; o; o >>= 1) s += __shfl_down_sync(0xffffffffu, s, o);
    if (lane == 0) g_hb[gw] = s;
}

// =================== K2: S[b][j][i] = masked(hw . mel + hb)  (frozen) ===================
__global__ void __launch_bounds__(256) k2_attn(const float* __restrict__ mel,
                                               const int* __restrict__ tlv,
                                               const int* __restrict__ mlv) {
    extern __shared__ float sm2[];
    float* melS = sm2;            // [80][132]
    float* hwS  = sm2 + 80*132;   // [80][129]
    int b  = blockIdx.z;
    int ml = mlv[b];
    int j0 = blockIdx.y * 128;
    if (j0 >= ml) return;
    int i0  = blockIdx.x * 128;
    int tid = threadIdx.x;
    int tx  = tid & 15;
    int ty  = tid >> 4;

    const float* melB = mel + (size_t)b*M_*TM_;
#pragma unroll
    for (int k = 0; k < 10; k++) {
        int l = tid + k*256;
        int m = l >> 5, j4 = l & 31;
        float4 v = *(const float4*)&melB[(size_t)m*TM_ + j0 + j4*4];
        *(float4*)&melS[m*132 + j4*4] = v;
    }
    const float* hwB = g_hw + (size_t)b*TT_*M_;
#pragma unroll
    for (int k = 0; k < 40; k++) {
        int l = tid + k*256;
        int m = l % 80, ii = l / 80;
        hwS[m*129 + ii] = hwB[(size_t)(i0+ii)*M_ + m];
    }
    __syncthreads();

    ull acc[8][4];
#pragma unroll
    for (int jk = 0; jk < 8; jk++)
#pragma unroll
        for (int p = 0; p < 4; p++) acc[jk][p] = 0ull;

#pragma unroll 2
    for (int m = 0; m < M_; m++) {
        float hv[8];
#pragma unroll
        for (int k = 0; k < 8; k++) hv[k] = hwS[m*129 + tx + 16*k];
        ull hp[4];
#pragma unroll
        for (int p = 0; p < 4; p++) hp[p] = pk2(hv[2*p], hv[2*p+1]);
#pragma unroll
        for (int jk = 0; jk < 8; jk++) {
            float mv = melS[m*132 + ty + 16*jk];
            ull mp = pk2(mv, mv);
#pragma unroll
            for (int p = 0; p < 4; p++) FMA2(acc[jk][p], hp[p], mp, acc[jk][p]);
        }
    }

    int tlb = tlv[b];
    float hbv[8];
    bool  msk[8];
#pragma unroll
    for (int k = 0; k < 8; k++) {
        int ig = i0 + tx + 16*k;
        hbv[k] = g_hb[b*TT_ + ig];
        msk[k] = (ig < tlb);
    }
#pragma unroll
    for (int jk = 0; jk < 8; jk++) {
        int j = j0 + ty + 16*jk;
        if (j < ml) {
            float* row = g_S + ((size_t)b*TM_ + j)*TT_ + i0;
#pragma unroll
            for (int p = 0; p < 4; p++) {
                float2 v = upk2(acc[jk][p]);
                int k0 = 2*p, k1 = 2*p + 1;
                row[tx + 16*k0] = msk[k0] ? (v.x + hbv[k0]) : NEGF;
                row[tx + 16*k1] = msk[k1] ? (v.y + hbv[k1]) : NEGF;
            }
        }
    }
}

// =================== K3: MAS DP — 4 warps/batch, wavefront lag, 4 rows/thread ===================
// Block = 128 threads. Thread tid owns rows 4*tid .. 4*tid+3 (warp w rows [128w,128w+127]).
// Warp w processes column group c = s - w at super-step s (4 columns/group).
// Cross-warp boundary (row 128w-1) flows through a 16-slot smem ring; slots written
// and read within a step are disjoint mod 16, and readers see values >=1 barrier old.
// Per step: process 4 cols + 1 __syncthreads. buf = 8 float4 ring (constant indexing).

// one column update: BU is this thread's float4 of S for column J
#define K3_COL(J, BU)                                                          \
{                                                                              \
    int j = (J);                                                               \
    if (j < ml) {                                                              \
        float cross = NEGF;                                                    \
        if (w > 0) cross = bndF[(w-1)*16 + ((j-1) & 15)];                      \
        float top = __shfl_up_sync(0xffffffffu, q3, 1);                        \
        if (lane == 0) top = cross;                                            \
        unsigned int mask = 1u << (j & 31);                                    \
        { float qs = q2;  if (qs > q3) cw3 |= mask; q3 = (BU).w + fmaxf(q3, qs); } \
        { float qs = q1;  if (qs > q2) cw2 |= mask; q2 = (BU).z + fmaxf(q2, qs); } \
        { float qs = q0;  if (qs > q1) cw1 |= mask; q1 = (BU).y + fmaxf(q1, qs); } \
        { float qs = top; if (qs > q0) cw0 |= mask; q0 = (BU).x + fmaxf(q0, qs); } \
        if (lane == 31) bndF[w*16 + (j & 15)] = q3;                            \
        if ((j & 31) == 31) {                                                  \
            unsigned int* crow = ch + ((j >> 5) << 2)*128 + tid;               \
            crow[0] = cw0; crow[128] = cw1; crow[256] = cw2; crow[384] = cw3;  \
            cw0 = cw1 = cw2 = cw3 = 0u;                                        \
        }                                                                      \
        int jn = j + 8; if (jn > jlim) jn = jlim;                              \
        (BU) = Sb4[(size_t)jn*128 + tid];                                      \
    }                                                                          \
}

#define K3_STEP(SVAR, BA, BB, BC, BD)                                          \
{                                                                              \
    int c_ = (SVAR) - w;                                                       \
    if (c_ >= 0 && c_ < nch) {                                                 \
        int jb_ = 1 + (c_ << 2);                                               \
        K3_COL(jb_ + 0, BA)                                                    \
        K3_COL(jb_ + 1, BB)                                                    \
        K3_COL(jb_ + 2, BC)                                                    \
        K3_COL(jb_ + 3, BD)                                                    \
    }                                                                          \
}

__global__ void __launch_bounds__(128) k3_dp(const float* __restrict__ ldp,
                                             const int* __restrict__ tlv,
                                             const int* __restrict__ mlv,
                                             float* __restrict__ out) {
    extern __shared__ unsigned int dsm3[];
    unsigned int* ch   = dsm3;                  // [64][4][128] choice bits
    unsigned int* dur  = dsm3 + 64*4*128;       // [512]
    float*        bndF = (float*)(dur + 512);   // [4][16] boundary ring
    unsigned int* auxU = (unsigned int*)(bndF + 64);   // [4] warp totals
    float*        auxF = (float*)(auxU);               // [4..7] loss partials (after)

    int b    = blockIdx.x;
    int tid  = threadIdx.x;
    int lane = tid & 31, w = tid >> 5;
    int tl = tlv[b], ml = mlv[b];
    int jlim = ml - 1;
    const float*  SbF = g_S + (size_t)b*TM_*TT_;
    const float4* Sb4 = (const float4*)SbF;     // column j starts at Sb4 + j*128

    float q0 = NEGF, q1 = NEGF, q2 = NEGF, q3 = NEGF;
    unsigned int cw0 = 0u, cw1 = 0u, cw2 = 0u, cw3 = 0u;
    if (tid == 0) q0 = SbF[0];

#pragma unroll
    for (int r = 0; r < 4; r++) dur[tid*4 + r] = 0u;
    if (tid < 64) bndF[tid] = NEGF;
    __syncthreads();

    // preload ring: buf[u] holds column 1 + (u XOR ((w&1)*4))  (phase-correct per warp)
    int xw = (w & 1) << 2;
    float4 b0 = Sb4[(size_t)(1 + (0 ^ xw))*128 + tid];
    float4 b1 = Sb4[(size_t)(1 + (1 ^ xw))*128 + tid];
    float4 b2 = Sb4[(size_t)(1 + (2 ^ xw))*128 + tid];
    float4 b3 = Sb4[(size_t)(1 + (3 ^ xw))*128 + tid];
    float4 b4 = Sb4[(size_t)(1 + (4 ^ xw))*128 + tid];
    float4 b5 = Sb4[(size_t)(1 + (5 ^ xw))*128 + tid];
    float4 b6 = Sb4[(size_t)(1 + (6 ^ xw))*128 + tid];
    float4 b7 = Sb4[(size_t)(1 + (7 ^ xw))*128 + tid];

    int nch   = (jlim + 3) >> 2;      // 4-column groups covering j=1..jlim
    int NS    = nch + 3;              // +3 steps of wavefront lag
    int niter = (NS + 1) >> 1;
    int s = 0;
    for (int it = 0; it < niter; it++) {
        K3_STEP(s,     b0, b1, b2, b3)
        __syncthreads();
        K3_STEP(s + 1, b4, b5, b6, b7)
        __syncthreads();
        s += 2;
    }
    // final partial flush
    if ((jlim & 31) != 31) {
        unsigned int* crow = ch + ((jlim >> 5) << 2)*128 + tid;
        crow[0] = cw0; crow[128] = cw1; crow[256] = cw2; crow[384] = cw3;
    }
    __syncthreads();

    if (tid == 0) {                    // serial CLZ run-scan backtrack
        int ii = tl - 1, jj = ml - 1;
        while (jj >= 0) {
            if (ii == 0) { dur[0] += (unsigned)(jj + 1); break; }
            unsigned int wv = ch[((jj >> 5)*4 + (ii & 3))*128 + (ii >> 2)];
            int bit = jj & 31;
            if (bit != 31) wv &= (2u << bit) - 1u;
            if (wv == 0) { dur[ii] += (unsigned)(bit + 1); jj -= bit + 1; }
            else {
                int hb = 31 - __clz(wv);
                int jp = (jj & ~31) + hb;
                dur[ii] += (unsigned)(jj - jp + 1);
                ii -= 1;
                jj = jp - 1;
            }
        }
    }
    __syncthreads();

    // ---- outputs: durations, loss partial, idx scatter ----
    unsigned int dv[4], tot = 0;
#pragma unroll
    for (int r = 0; r < 4; r++) { dv[r] = dur[tid*4 + r]; tot += dv[r]; }

    float ls = 0.f;
#pragma unroll
    for (int r = 0; r < 4; r++) {
        int row = tid*4 + r;
        out[DUR_OFF + b*TT_ + row] = (float)dv[r];
        if (row < tl) {
            float lg = logf(fmaxf((float)dv[r], 1.0f));
            float df = ldp[b*TT_ + row] - lg;
            ls += df * df;
        }
    }
#pragma unroll
    for (int o = 16; o; o >>= 1) ls += __shfl_down_sync(0xffffffffu, ls, o);

    unsigned int v = tot;
#pragma unroll
    for (int o = 1; o < 32; o <<= 1) {
        unsigned int t = __shfl_up_sync(0xffffffffu, v, o);
        if (lane >= o) v += t;
    }
    if (lane == 31) auxU[w] = v;            // warp duration totals
    if (lane == 0)  auxF[4 + w] = ls;       // warp loss partials
    __syncthreads();
    if (tid == 0) {
        g_lsq[b]  = auxF[4] + auxF[5] + auxF[6] + auxF[7];
        g_lcnt[b] = (float)tl;
    }
    unsigned int off = 0;
#pragma unroll
    for (int k = 0; k < 4; k++) if (k < w) off += auxU[k];
    unsigned int pos = off + v - tot;       // exclusive prefix for this thread
#pragma unroll
    for (int r = 0; r < 4; r++) {
        int row = tid*4 + r;
        for (unsigned int kk = 0; kk < dv[r]; kk++) g_idx[b*TM_ + pos + kk] = row;
        pos += dv[r];
    }
}

// =================== K5: length-regulate expansion (+ fused loss reduce) ===================
__global__ void __launch_bounds__(256) k5_expand(const float* __restrict__ h,
                                                 const int* __restrict__ mlv,
                                                 float* __restrict__ out) {
    if (blockIdx.y == 0 && blockIdx.z == 0 && threadIdx.x < 32) {
        float s = g_lsq[threadIdx.x], cc = g_lcnt[threadIdx.x];
#pragma unroll
        for (int o = 16; o; o >>= 1) {
            s  += __shfl_down_sync(0xffffffffu, s, o);
            cc += __shfl_down_sync(0xffffffffu, cc, o);
        }
        if (threadIdx.x == 0) out[LOSS_OFF] = s / cc;
    }
    int b  = blockIdx.z;
    int j  = blockIdx.y * 2 + (threadIdx.x >> 7);
    int c4 = threadIdx.x & 127;
    int ml = mlv[b];
    float4 v;
    if (j < ml) {
        int idx = g_idx[b*TM_ + j];
        v = *(const float4*)&h[((size_t)(b*TT_ + idx))*D_ + c4*4];
    } else {
        v = make_float4(0.f, 0.f, 0.f, 0.f);
    }
    *(float4*)&out[((size_t)(b*TM_ + j))*D_ + c4*4] = v;
}

// =================== host launcher ===================
extern "C" void kernel_launch(void* const* d_in, const int* in_sizes, int n_in,
                              void* d_out, int out_size) {
    const float* h_text = (const float*)d_in[0];   // [32,512,512]
    const float* mel    = (const float*)d_in[1];   // [32,80,2048]
    const int*   tl     = (const int*)  d_in[2];   // [32]
    const int*   mlv    = (const int*)  d_in[3];   // [32]
    const float* w_proj = (const float*)d_in[4];   // [512,80]
    const float* b_proj = (const float*)d_in[5];   // [512]
    const float* ldp    = (const float*)d_in[6];   // [32,512]
    float* out = (float*)d_out;

    const int K2_SMEM = (80*132 + 80*129) * 4;                 // 83520
    const int K3_SMEM = (64*4*128 + 512 + 64 + 8) * 4;         // 133456
    cudaFuncSetAttribute(k2_attn, cudaFuncAttributeMaxDynamicSharedMemorySize, K2_SMEM);
    cudaFuncSetAttribute(k3_dp,   cudaFuncAttributeMaxDynamicSharedMemorySize, K3_SMEM);

    k1_hw<<<256, 256>>>(h_text, w_proj);
    k1_hb<<<2048, 256>>>(h_text, b_proj);
    k2_attn<<<dim3(4, 16, 32), 256, K2_SMEM>>>(mel, tl, mlv);
    k3_dp<<<32, 128, K3_SMEM>>>(ldp, tl, mlv, out);
    k5_expand<<<dim3(1, 1024, 32), 256>>>(h_text, mlv, out);
}

// round 11
// speedup vs baseline: 1.8714x; 1.8714x over previous
#include <cuda_runtime.h>
#include <math.h>

#define B_   32
#define TT_  512
#define TM_  2048
#define D_   512
#define M_   80
#define NEGF (-1e9f)

#define HEXP_ELEMS (B_*TM_*D_)       /* 33554432 */
#define LOSS_OFF   HEXP_ELEMS
#define DUR_OFF    (HEXP_ELEMS + 1)

typedef unsigned long long ull;

// ------------------- device scratch (no allocation allowed) -------------------
__device__ float g_hw[B_*TT_*M_];         // [b*Tt+i][80] = h @ W
__device__ float g_hb[B_*TT_];            // h @ b_proj
__device__ float g_S[(size_t)B_*TM_*TT_]; // [b][j][i] masked scores (128 MB)
__device__ int   g_idx[B_*TM_];           // frame -> token index
__device__ float g_lsq[B_];
__device__ float g_lcnt[B_];

// ------------------- f32x2 helpers -------------------
__device__ __forceinline__ ull pk2(float x, float y) {
    ull r;
    asm("mov.b64 %0, {%1,%2};" : "=l"(r) : "f"(x), "f"(y));
    return r;
}
__device__ __forceinline__ float2 upk2(ull v) {
    float2 r;
    asm("mov.b64 {%0,%1}, %2;" : "=f"(r.x), "=f"(r.y) : "l"(v));
    return r;
}
#define FMA2(d, a, b, c) asm("fma.rn.f32x2 %0, %1, %2, %3;" : "=l"(d) : "l"(a), "l"(b), "l"(c))

// =================== K1: hw[b,i,m] = sum_d h[b,i,d] * w[d,m]  (frozen) ===================
__global__ void __launch_bounds__(256) k1_hw(const float* __restrict__ h,
                                             const float* __restrict__ w) {
    __shared__ float hS[64*68];   // [r][d] stride 68
    __shared__ float wS[64*84];   // [d][m] stride 84
    int tid  = threadIdx.x;
    int row0 = blockIdx.x * 64;
    int tx = tid & 15;
    int ty = tid >> 4;
    float acc[4][5];
#pragma unroll
    for (int r = 0; r < 4; r++)
#pragma unroll
        for (int m = 0; m < 5; m++) acc[r][m] = 0.f;

    for (int dc = 0; dc < D_; dc += 64) {
#pragma unroll
        for (int k = 0; k < 4; k++) {
            int l = tid + k*256;
            int r = l >> 4, d4 = l & 15;
            float4 v = *(const float4*)&h[(size_t)(row0 + r)*D_ + dc + d4*4];
            *(float4*)&hS[r*68 + d4*4] = v;
        }
#pragma unroll
        for (int k = 0; k < 5; k++) {
            int l = tid + k*256;
            int d = l / 20, m4 = l % 20;
            float4 v = *(const float4*)&w[(size_t)(dc + d)*M_ + m4*4];
            *(float4*)&wS[d*84 + m4*4] = v;
        }
        __syncthreads();
#pragma unroll 8
        for (int d = 0; d < 64; d++) {
            float a0 = hS[(ty*4+0)*68 + d];
            float a1 = hS[(ty*4+1)*68 + d];
            float a2 = hS[(ty*4+2)*68 + d];
            float a3 = hS[(ty*4+3)*68 + d];
#pragma unroll
            for (int m = 0; m < 5; m++) {
                float bv = wS[d*84 + tx*5 + m];
                acc[0][m] += a0*bv; acc[1][m] += a1*bv;
                acc[2][m] += a2*bv; acc[3][m] += a3*bv;
            }
        }
        __syncthreads();
    }
#pragma unroll
    for (int r = 0; r < 4; r++)
#pragma unroll
        for (int m = 0; m < 5; m++)
            g_hw[(size_t)(row0 + ty*4 + r)*M_ + tx*5 + m] = acc[r][m];
}

// =================== K1b: hb[row] = h[row,:] . b_proj  (frozen) ===================
__global__ void k1_hb(const float* __restrict__ h, const float* __restrict__ bp) {
    int gw   = (blockIdx.x*blockDim.x + threadIdx.x) >> 5;
    int lane = threadIdx.x & 31;
    if (gw >= B_*TT_) return;
    const float4* hr = (const float4*)&h[(size_t)gw * D_];
    const float4* b4 = (const float4*)bp;
    float s = 0.f;
    for (int k = lane; k < D_/4; k += 32) {
        float4 a = hr[k], c = b4[k];
        s += a.x*c.x + a.y*c.y + a.z*c.z + a.w*c.w;
    }
#pragma unroll
    for (int o = 16; o; o >>= 1) s += __shfl_down_sync(0xffffffffu, s, o);
    if (lane == 0) g_hb[gw] = s;
}

// =================== K2: S[b][j][i] = masked(hw . mel + hb)  (frozen) ===================
__global__ void __launch_bounds__(256) k2_attn(const float* __restrict__ mel,
                                               const int* __restrict__ tlv,
                                               const int* __restrict__ mlv) {
    extern __shared__ float sm2[];
    float* melS = sm2;            // [80][132]
    float* hwS  = sm2 + 80*132;   // [80][129]
    int b  = blockIdx.z;
    int ml = mlv[b];
    int j0 = blockIdx.y * 128;
    if (j0 >= ml) return;
    int i0  = blockIdx.x * 128;
    int tid = threadIdx.x;
    int tx  = tid & 15;
    int ty  = tid >> 4;

    const float* melB = mel + (size_t)b*M_*TM_;
#pragma unroll
    for (int k = 0; k < 10; k++) {
        int l = tid + k*256;
        int m = l >> 5, j4 = l & 31;
        float4 v = *(const float4*)&melB[(size_t)m*TM_ + j0 + j4*4];
        *(float4*)&melS[m*132 + j4*4] = v;
    }
    const float* hwB = g_hw + (size_t)b*TT_*M_;
#pragma unroll
    for (int k = 0; k < 40; k++) {
        int l = tid + k*256;
        int m = l % 80, ii = l / 80;
        hwS[m*129 + ii] = hwB[(size_t)(i0+ii)*M_ + m];
    }
    __syncthreads();

    ull acc[8][4];
#pragma unroll
    for (int jk = 0; jk < 8; jk++)
#pragma unroll
        for (int p = 0; p < 4; p++) acc[jk][p] = 0ull;

#pragma unroll 2
    for (int m = 0; m < M_; m++) {
        float hv[8];
#pragma unroll
        for (int k = 0; k < 8; k++) hv[k] = hwS[m*129 + tx + 16*k];
        ull hp[4];
#pragma unroll
        for (int p = 0; p < 4; p++) hp[p] = pk2(hv[2*p], hv[2*p+1]);
#pragma unroll
        for (int jk = 0; jk < 8; jk++) {
            float mv = melS[m*132 + ty + 16*jk];
            ull mp = pk2(mv, mv);
#pragma unroll
            for (int p = 0; p < 4; p++) FMA2(acc[jk][p], hp[p], mp, acc[jk][p]);
        }
    }

    int tlb = tlv[b];
    float hbv[8];
    bool  msk[8];
#pragma unroll
    for (int k = 0; k < 8; k++) {
        int ig = i0 + tx + 16*k;
        hbv[k] = g_hb[b*TT_ + ig];
        msk[k] = (ig < tlb);
    }
#pragma unroll
    for (int jk = 0; jk < 8; jk++) {
        int j = j0 + ty + 16*jk;
        if (j < ml) {
            float* row = g_S + ((size_t)b*TM_ + j)*TT_ + i0;
#pragma unroll
            for (int p = 0; p < 4; p++) {
                float2 v = upk2(acc[jk][p]);
                int k0 = 2*p, k1 = 2*p + 1;
                row[tx + 16*k0] = msk[k0] ? (v.x + hbv[k0]) : NEGF;
                row[tx + 16*k1] = msk[k1] ? (v.y + hbv[k1]) : NEGF;
            }
        }
    }
}

// =================== K3: MAS DP — R5 structure + ghost rows (4 cols / barrier) ===================
// 512 threads (16 warps), thread = text row, ALL warps process the same column.
// Per 4-column round: warp w>0 reads rows 32w-4..32w-1 (published at col j0-1) and
// redundantly advances 3 ghost rows to supply lane-0 boundaries for j0+1..j0+3.
// One __syncthreads per round (4x fewer than R5). Backtrack/epilogue = R5 verbatim.
__global__ void __launch_bounds__(512) k3_dp(const float* __restrict__ ldp,
                                             const int* __restrict__ tlv,
                                             const int* __restrict__ mlv,
                                             float* __restrict__ out) {
    extern __shared__ unsigned int dsm3[];
    unsigned int* ch   = dsm3;                        // [512][65] choice bits
    unsigned int* dur  = dsm3 + 512*65;               // [512]
    unsigned int* wsum = dur + 512;                   // [16]
    float*        red  = (float*)(wsum + 16);         // [16]
    float*        Pb   = (float*)(red + 16);          // [2][16][4] published boundary q

    int b    = blockIdx.x;
    int tid  = threadIdx.x;
    int lane = tid & 31, wd = tid >> 5;
    int tl = tlv[b], ml = mlv[b];
    int jlim = ml - 1;
    const float* Sb = g_S + (size_t)b*TM_*TT_;

    float q = (tid == 0) ? Sb[0] : NEGF;
    unsigned int cw = 0;

    // prefetch buffers: groups of 16 columns, loaded 2 groups ahead
    float cur[16], nxt[16], pf[16];
#pragma unroll
    for (int k = 0; k < 16; k++) {
        int j = 1 + k; if (j > jlim) j = jlim;
        cur[k] = Sb[(size_t)j*TT_ + tid];
    }
#pragma unroll
    for (int k = 0; k < 16; k++) {
        int j = 17 + k; if (j > jlim) j = jlim;
        nxt[k] = Sb[(size_t)j*TT_ + tid];
    }

    // publish column-0 boundary state
    if (lane >= 28) Pb[wd*4 + (lane - 28)] = q;       // parity 0
    __syncthreads();

    int nrounds = (jlim + 3) >> 2;                    // 4-column rounds covering j=1..jlim
    int ngroups = (nrounds + 3) >> 2;                 // 16-column groups
    int rr = 0;
    for (int g = 0; g < ngroups; g++) {
        int jbase = 1 + (g << 4);
        // prefetch group g+2
#pragma unroll
        for (int k = 0; k < 16; k++) {
            int j = jbase + 32 + k; if (j > jlim) j = jlim;
            pf[k] = Sb[(size_t)j*TT_ + tid];
        }
#pragma unroll
        for (int r4 = 0; r4 < 4; r4++) {
            int j0 = jbase + (r4 << 2);
            if (j0 <= jlim) {                          // block-uniform
                int par = rr & 1;
                float g1 = NEGF, g2 = NEGF, g3 = NEGF, g4 = NEGF;
                float s10 = 0.f, s11 = 0.f, s12 = 0.f, s20 = 0.f, s21 = 0.f, s30 = 0.f;
                if (wd > 0) {
                    const float* Pr = Pb + par*64 + (wd - 1)*4;
                    g4 = Pr[0]; g3 = Pr[1]; g2 = Pr[2]; g1 = Pr[3];
                    int c1 = j0 + 1 > jlim ? jlim : j0 + 1;
                    int c2 = j0 + 2 > jlim ? jlim : j0 + 2;
                    int R1 = (wd << 5) - 1;            // row 32w-1
                    s10 = Sb[(size_t)j0*TT_ + R1];
                    s11 = Sb[(size_t)c1*TT_ + R1];
                    s12 = Sb[(size_t)c2*TT_ + R1];
                    s20 = Sb[(size_t)j0*TT_ + R1 - 1];
                    s21 = Sb[(size_t)c1*TT_ + R1 - 1];
                    s30 = Sb[(size_t)j0*TT_ + R1 - 2];
                }
#pragma unroll
                for (int k = 0; k < 4; k++) {
                    int j = j0 + k;
                    if (j <= jlim) {                   // block-uniform
                        float up = __shfl_up_sync(0xffffffffu, q, 1);
                        if (lane == 0) up = g1;
                        unsigned int take = (up > q) ? 1u : 0u;
                        q = cur[(r4 << 2) + k] + fmaxf(q, up);
                        cw |= take << (j & 31);
                        if ((j & 31) == 31) { ch[tid*65 + (j >> 5)] = cw; cw = 0u; }
                        if (wd > 0) {                   // ghost advance to column j
                            if (k == 0) {
                                float t1 = s10 + fmaxf(g1, g2);
                                float t2 = s20 + fmaxf(g2, g3);
                                float t3 = s30 + fmaxf(g3, g4);
                                g1 = t1; g2 = t2; g3 = t3;
                            } else if (k == 1) {
                                float t1 = s11 + fmaxf(g1, g2);
                                float t2 = s21 + fmaxf(g2, g3);
                                g1 = t1; g2 = t2;
                            } else if (k == 2) {
                                g1 = s12 + fmaxf(g1, g2);
                            }
                        }
                    }
                }
                if (lane >= 28) Pb[(par ^ 1)*64 + wd*4 + (lane - 28)] = q;
            }
            __syncthreads();
            rr++;
        }
#pragma unroll
        for (int k = 0; k < 16; k++) { cur[k] = nxt[k]; nxt[k] = pf[k]; }
    }
    if (((ml - 1) & 31) != 31) ch[tid*65 + ((ml - 1) >> 5)] = cw;
    dur[tid] = 0u;
    __syncthreads();

    if (tid == 0) {                     // serial CLZ run-scan backtrack (R5 verbatim)
        int ii = tl - 1, jj = ml - 1;
        while (jj >= 0) {
            if (ii == 0) { dur[0] += (unsigned)(jj + 1); break; }
            unsigned int wv = ch[ii*65 + (jj >> 5)];
            int bit = jj & 31;
            if (bit != 31) wv &= (2u << bit) - 1u;
            if (wv == 0) { dur[ii] += (unsigned)(bit + 1); jj -= bit + 1; }
            else {
                int hb = 31 - __clz(wv);
                int jp = (jj & ~31) + hb;
                dur[ii] += (unsigned)(jj - jp + 1);
                ii -= 1;
                jj = jp - 1;
            }
        }
    }
    __syncthreads();

    // ---- outputs (R5 verbatim) ----
    unsigned int d = dur[tid];
    out[DUR_OFF + b*TT_ + tid] = (float)d;

    float part = 0.f;
    if (tid < tl) {
        float lg = logf(fmaxf((float)d, 1.0f));
        float df = ldp[b*TT_ + tid] - lg;
        part = df * df;
    }
#pragma unroll
    for (int o = 16; o; o >>= 1) part += __shfl_down_sync(0xffffffffu, part, o);
    if (lane == 0) red[wd] = part;

    unsigned int v = d;
#pragma unroll
    for (int o = 1; o < 32; o <<= 1) {
        unsigned int t = __shfl_up_sync(0xffffffffu, v, o);
        if (lane >= o) v += t;
    }
    if (lane == 31) wsum[wd] = v;
    __syncthreads();
    if (tid < 16) {
        unsigned int s2 = wsum[tid];
#pragma unroll
        for (int o = 1; o < 16; o <<= 1) {
            unsigned int t = __shfl_up_sync(0x0000ffffu, s2, o);
            if ((tid & 15) >= o) s2 += t;
        }
        wsum[tid] = s2;
        float ls = red[tid];
#pragma unroll
        for (int o = 8; o; o >>= 1) ls += __shfl_down_sync(0x0000ffffu, ls, o);
        if (tid == 0) { g_lsq[b] = ls; g_lcnt[b] = (float)tl; }
    }
    __syncthreads();
    unsigned int base = (wd == 0) ? 0u : wsum[wd - 1];
    unsigned int cend = base + v;
    unsigned int cstart = cend - d;
    for (unsigned int j = cstart; j < cend; j++) g_idx[b*TM_ + j] = tid;
}

// =================== K5: length-regulate expansion (+ fused loss reduce) ===================
__global__ void __launch_bounds__(256) k5_expand(const float* __restrict__ h,
                                                 const int* __restrict__ mlv,
                                                 float* __restrict__ out) {
    if (blockIdx.y == 0 && blockIdx.z == 0 && threadIdx.x < 32) {
        float s = g_lsq[threadIdx.x], cc = g_lcnt[threadIdx.x];
#pragma unroll
        for (int o = 16; o; o >>= 1) {
            s  += __shfl_down_sync(0xffffffffu, s, o);
            cc += __shfl_down_sync(0xffffffffu, cc, o);
        }
        if (threadIdx.x == 0) out[LOSS_OFF] = s / cc;
    }
    int b  = blockIdx.z;
    int j  = blockIdx.y * 2 + (threadIdx.x >> 7);
    int c4 = threadIdx.x & 127;
    int ml = mlv[b];
    float4 v;
    if (j < ml) {
        int idx = g_idx[b*TM_ + j];
        v = *(const float4*)&h[((size_t)(b*TT_ + idx))*D_ + c4*4];
    } else {
        v = make_float4(0.f, 0.f, 0.f, 0.f);
    }
    *(float4*)&out[((size_t)(b*TM_ + j))*D_ + c4*4] = v;
}

// =================== host launcher ===================
extern "C" void kernel_launch(void* const* d_in, const int* in_sizes, int n_in,
                              void* d_out, int out_size) {
    const float* h_text = (const float*)d_in[0];   // [32,512,512]
    const float* mel    = (const float*)d_in[1];   // [32,80,2048]
    const int*   tl     = (const int*)  d_in[2];   // [32]
    const int*   mlv    = (const int*)  d_in[3];   // [32]
    const float* w_proj = (const float*)d_in[4];   // [512,80]
    const float* b_proj = (const float*)d_in[5];   // [512]
    const float* ldp    = (const float*)d_in[6];   // [32,512]
    float* out = (float*)d_out;

    const int K2_SMEM = (80*132 + 80*129) * 4;                           // 83520
    const int K3_SMEM = (512*65 + 512 + 16 + 16) * 4 + 2*16*4*4;         // 135872
    cudaFuncSetAttribute(k2_attn, cudaFuncAttributeMaxDynamicSharedMemorySize, K2_SMEM);
    cudaFuncSetAttribute(k3_dp,   cudaFuncAttributeMaxDynamicSharedMemorySize, K3_SMEM);

    k1_hw<<<256, 256>>>(h_text, w_proj);            // launch 1
    k1_hb<<<2048, 256>>>(h_text, b_proj);           // launch 2
    k2_attn<<<dim3(4, 16, 32), 256, K2_SMEM>>>(mel, tl, mlv);   // launch 3
    k3_dp<<<32, 512, K3_SMEM>>>(ldp, tl, mlv, out); // launch 4  <- ncu captures this
    k5_expand<<<dim3(1, 1024, 32), 256>>>(h_text, mlv, out);    // launch 5
}